// round 5
// baseline (speedup 1.0000x reference)
#include <cuda_runtime.h>
#include <cstdint>

// WaveletNet: 4 lifting steps with length-1 filters == elementwise 2x2 linear map.
// Evens half of each output row: m00*e + m01*o ; details half: m10*e + m11*o,
// with M = prod_{k=3..0} [[1-u_k p_k, u_k], [-p_k, 1]].
// R5: 256-bit vector ld/st (sm_100+ v8.f32). Each thread: 2 octs = 64B read,
// one 32B store to the evens half + one 32B store to the odds half.

#define L_FULL 65536
#define L_HALF 32768
#define B_DIM  256
#define FLOATS_PER_THREAD 16
#define THREADS_PER_ROW (L_FULL / FLOATS_PER_THREAD)   // 4096
#define TPR_SHIFT 12
#define TPR_MASK  (THREADS_PER_ROW - 1)
#define N_THREADS ((long long)B_DIM * THREADS_PER_ROW) // 1,048,576
#define Z_ELEMS ((long long)B_DIM * L_FULL)            // 16,777,216
#define THREADS 256

__device__ __forceinline__ void ldg_v8(const float* p, float* r) {
    asm volatile("ld.global.nc.v8.f32 {%0,%1,%2,%3,%4,%5,%6,%7}, [%8];"
                 : "=f"(r[0]), "=f"(r[1]), "=f"(r[2]), "=f"(r[3]),
                   "=f"(r[4]), "=f"(r[5]), "=f"(r[6]), "=f"(r[7])
                 : "l"(p));
}

__device__ __forceinline__ void stg_cs_v8(float* p, const float* r) {
    asm volatile("st.global.cs.v8.f32 [%8], {%0,%1,%2,%3,%4,%5,%6,%7};"
                 :: "f"(r[0]), "f"(r[1]), "f"(r[2]), "f"(r[3]),
                    "f"(r[4]), "f"(r[5]), "f"(r[6]), "f"(r[7]),
                    "l"(p)
                 : "memory");
}

__global__ void __launch_bounds__(THREADS)
wavelet_fused_kernel(const float* __restrict__ x,
                     const float* __restrict__ P,
                     const float* __restrict__ U,
                     float* __restrict__ out,
                     long long out_size)
{
    // Compose the 4 lifting steps into one 2x2 matrix (coeffs L1-cached, cheap).
    float m00 = 1.f, m01 = 0.f, m10 = 0.f, m11 = 1.f;
#pragma unroll
    for (int k = 0; k < 4; k++) {
        float p = __ldg(&P[k]);
        float u = __ldg(&U[k]);
        float a00 = 1.f - u * p, a01 = u;
        float a10 = -p,          a11 = 1.f;
        float n00 = a00 * m00 + a01 * m10;
        float n01 = a00 * m01 + a01 * m11;
        float n10 = a10 * m00 + a11 * m10;
        float n11 = a10 * m01 + a11 * m11;
        m00 = n00; m01 = n01; m10 = n10; m11 = n11;
    }

    long long g = (long long)blockIdx.x * THREADS + threadIdx.x;

    long long b = g >> TPR_SHIFT;
    long long t = g & TPR_MASK;

    // Front-batched 2x 256-bit loads (16 consecutive floats = 8 (e,o) pairs).
    const float* src = x + g * FLOATS_PER_THREAD;
    float v[16];
    ldg_v8(src,     v);
    ldg_v8(src + 8, v + 8);

    float ev[8], od[8];
#pragma unroll
    for (int i = 0; i < 8; i++) {
        float e = v[2 * i], o = v[2 * i + 1];
        ev[i] = m00 * e + m01 * o;
        od[i] = m10 * e + m11 * o;
    }

    float* row = out + b * (long long)L_FULL;
    long long i0 = 8 * t;                     // 8 pairs per thread -> 32B aligned
    stg_cs_v8(row + i0,          ev);         // evens half
    stg_cs_v8(row + L_HALF + i0, od);         // details half

    // log_det (and any padding beyond z) = 0
    if (g == 0) {
        for (long long i = Z_ELEMS; i < out_size; i++) out[i] = 0.0f;
    }
}

extern "C" void kernel_launch(void* const* d_in, const int* in_sizes, int n_in,
                              void* d_out, int out_size)
{
    const float* x = (const float*)d_in[0];
    const float* P = (const float*)d_in[1];
    const float* U = (const float*)d_in[2];
    float* out = (float*)d_out;

    const int blocks = (int)(N_THREADS / THREADS);  // 4096, exact cover
    wavelet_fused_kernel<<<blocks, THREADS>>>(x, P, U, out, (long long)out_size);
}

// round 6
// speedup vs baseline: 1.0591x; 1.0591x over previous
#include <cuda_runtime.h>

// WaveletNet: 4 lifting steps with length-1 filters == elementwise 2x2 linear map.
// Evens half of each output row: m00*e + m01*o ; details half: m10*e + m11*o,
// with M = prod_{k=3..0} [[1-u_k p_k, u_k], [-p_k, 1]].
// R6: R4 structure (2 octs/thread, 4x LDG.128 front-batched, 4x STG.128),
// stores switched to write-through (.wt) to avoid dirty-L2 writeback interference.

#define L_FULL 65536
#define L_HALF 32768
#define B_DIM  256
#define OCTS_PER_ROW (L_FULL / 8)          // 8192 (one oct = 8 floats = 4 pairs)
#define OCT_SHIFT 13
#define OCT_MASK  (OCTS_PER_ROW - 1)
#define N_OCTS ((long long)B_DIM * OCTS_PER_ROW)   // 2,097,152
#define Z_ELEMS ((long long)B_DIM * L_FULL)        // 16,777,216
#define THREADS 256
#define OCTS_PER_THREAD 2
#define OCTS_PER_BLOCK (THREADS * OCTS_PER_THREAD) // 512

__device__ __forceinline__ void stg_wt_v4(float* p, float4 v) {
    asm volatile("st.global.wt.v4.f32 [%4], {%0,%1,%2,%3};"
                 :: "f"(v.x), "f"(v.y), "f"(v.z), "f"(v.w), "l"(p)
                 : "memory");
}

__global__ void __launch_bounds__(THREADS)
wavelet_fused_kernel(const float4* __restrict__ x4,
                     const float* __restrict__ P,
                     const float* __restrict__ U,
                     float* __restrict__ out,
                     long long out_size)
{
    // Compose the 4 lifting steps into one 2x2 matrix (coeffs L1-cached, cheap).
    float m00 = 1.f, m01 = 0.f, m10 = 0.f, m11 = 1.f;
#pragma unroll
    for (int k = 0; k < 4; k++) {
        float p = __ldg(&P[k]);
        float u = __ldg(&U[k]);
        float a00 = 1.f - u * p, a01 = u;
        float a10 = -p,          a11 = 1.f;
        float n00 = a00 * m00 + a01 * m10;
        float n01 = a00 * m01 + a01 * m11;
        float n10 = a10 * m00 + a11 * m10;
        float n11 = a10 * m01 + a11 * m11;
        m00 = n00; m01 = n01; m10 = n10; m11 = n11;
    }

    // Two octs per thread, blockDim apart (both fully coalesced at warp level).
    long long g0 = (long long)blockIdx.x * OCTS_PER_BLOCK + threadIdx.x;
    long long g1 = g0 + THREADS;

    // Front-batched loads: 4 independent LDG.128 before any arithmetic.
    const float4* s0 = x4 + 2 * g0;
    const float4* s1 = x4 + 2 * g1;
    float4 a0 = __ldg(s0);
    float4 a1 = __ldg(s0 + 1);
    float4 b0 = __ldg(s1);
    float4 b1 = __ldg(s1 + 1);

    float4 ev0, od0, ev1, od1;
    ev0.x = m00 * a0.x + m01 * a0.y;  od0.x = m10 * a0.x + m11 * a0.y;
    ev0.y = m00 * a0.z + m01 * a0.w;  od0.y = m10 * a0.z + m11 * a0.w;
    ev0.z = m00 * a1.x + m01 * a1.y;  od0.z = m10 * a1.x + m11 * a1.y;
    ev0.w = m00 * a1.z + m01 * a1.w;  od0.w = m10 * a1.z + m11 * a1.w;

    ev1.x = m00 * b0.x + m01 * b0.y;  od1.x = m10 * b0.x + m11 * b0.y;
    ev1.y = m00 * b0.z + m01 * b0.w;  od1.y = m10 * b0.z + m11 * b0.w;
    ev1.z = m00 * b1.x + m01 * b1.y;  od1.z = m10 * b1.x + m11 * b1.y;
    ev1.w = m00 * b1.z + m01 * b1.w;  od1.w = m10 * b1.z + m11 * b1.w;

    {
        long long b = g0 >> OCT_SHIFT;
        long long q = g0 & OCT_MASK;
        float* row = out + b * (long long)L_FULL;
        long long i = 4 * q;
        stg_wt_v4(row + i, ev0);
        stg_wt_v4(row + L_HALF + i, od0);
    }
    {
        long long b = g1 >> OCT_SHIFT;
        long long q = g1 & OCT_MASK;
        float* row = out + b * (long long)L_FULL;
        long long i = 4 * q;
        stg_wt_v4(row + i, ev1);
        stg_wt_v4(row + L_HALF + i, od1);
    }

    // log_det (and any padding beyond z) = 0
    if (g0 == 0) {
        for (long long i = Z_ELEMS; i < out_size; i++) out[i] = 0.0f;
    }
}

extern "C" void kernel_launch(void* const* d_in, const int* in_sizes, int n_in,
                              void* d_out, int out_size)
{
    const float4* x4 = (const float4*)d_in[0];
    const float*  P  = (const float*)d_in[1];
    const float*  U  = (const float*)d_in[2];
    float* out = (float*)d_out;

    const int blocks = (int)(N_OCTS / OCTS_PER_BLOCK);  // 4096, exact cover
    wavelet_fused_kernel<<<blocks, THREADS>>>(x4, P, U, out, (long long)out_size);
}

// round 7
// speedup vs baseline: 1.1614x; 1.0965x over previous
#include <cuda_runtime.h>

// WaveletNet: 4 lifting steps with length-1 filters == elementwise 2x2 linear map.
// Evens half of each output row: m00*e + m01*o ; details half: m10*e + m11*o,
// with M = prod_{k=3..0} [[1-u_k p_k, u_k], [-p_k, 1]].
// R7 (final form): R4 structure — 2 octs/thread, 4x front-batched 128-bit loads,
// 4x STG.128 evict-first stores — with L2-only (.cg) loads (no L1 reuse exists).
// Kernel is at the compulsory-traffic memory floor: 128MB / ~18us ≈ 7.1 TB/s combined.

#define L_FULL 65536
#define L_HALF 32768
#define B_DIM  256
#define OCTS_PER_ROW (L_FULL / 8)          // 8192 (one oct = 8 floats = 4 pairs)
#define OCT_SHIFT 13
#define OCT_MASK  (OCTS_PER_ROW - 1)
#define N_OCTS ((long long)B_DIM * OCTS_PER_ROW)   // 2,097,152
#define Z_ELEMS ((long long)B_DIM * L_FULL)        // 16,777,216
#define THREADS 256
#define OCTS_PER_THREAD 2
#define OCTS_PER_BLOCK (THREADS * OCTS_PER_THREAD) // 512

__device__ __forceinline__ float4 ldg_cg_v4(const float4* p) {
    float4 v;
    asm volatile("ld.global.cg.v4.f32 {%0,%1,%2,%3}, [%4];"
                 : "=f"(v.x), "=f"(v.y), "=f"(v.z), "=f"(v.w)
                 : "l"(p));
    return v;
}

__global__ void __launch_bounds__(THREADS)
wavelet_fused_kernel(const float4* __restrict__ x4,
                     const float* __restrict__ P,
                     const float* __restrict__ U,
                     float* __restrict__ out,
                     long long out_size)
{
    // Compose the 4 lifting steps into one 2x2 matrix (coeffs L1-cached, cheap).
    float m00 = 1.f, m01 = 0.f, m10 = 0.f, m11 = 1.f;
#pragma unroll
    for (int k = 0; k < 4; k++) {
        float p = __ldg(&P[k]);
        float u = __ldg(&U[k]);
        float a00 = 1.f - u * p, a01 = u;
        float a10 = -p,          a11 = 1.f;
        float n00 = a00 * m00 + a01 * m10;
        float n01 = a00 * m01 + a01 * m11;
        float n10 = a10 * m00 + a11 * m10;
        float n11 = a10 * m01 + a11 * m11;
        m00 = n00; m01 = n01; m10 = n10; m11 = n11;
    }

    // Two octs per thread, blockDim apart (both fully coalesced at warp level).
    long long g0 = (long long)blockIdx.x * OCTS_PER_BLOCK + threadIdx.x;
    long long g1 = g0 + THREADS;

    // Front-batched loads: 4 independent LDG.128 (L2-only) before any arithmetic.
    const float4* s0 = x4 + 2 * g0;
    const float4* s1 = x4 + 2 * g1;
    float4 a0 = ldg_cg_v4(s0);
    float4 a1 = ldg_cg_v4(s0 + 1);
    float4 b0 = ldg_cg_v4(s1);
    float4 b1 = ldg_cg_v4(s1 + 1);

    float4 ev0, od0, ev1, od1;
    ev0.x = m00 * a0.x + m01 * a0.y;  od0.x = m10 * a0.x + m11 * a0.y;
    ev0.y = m00 * a0.z + m01 * a0.w;  od0.y = m10 * a0.z + m11 * a0.w;
    ev0.z = m00 * a1.x + m01 * a1.y;  od0.z = m10 * a1.x + m11 * a1.y;
    ev0.w = m00 * a1.z + m01 * a1.w;  od0.w = m10 * a1.z + m11 * a1.w;

    ev1.x = m00 * b0.x + m01 * b0.y;  od1.x = m10 * b0.x + m11 * b0.y;
    ev1.y = m00 * b0.z + m01 * b0.w;  od1.y = m10 * b0.z + m11 * b0.w;
    ev1.z = m00 * b1.x + m01 * b1.y;  od1.z = m10 * b1.x + m11 * b1.y;
    ev1.w = m00 * b1.z + m01 * b1.w;  od1.w = m10 * b1.z + m11 * b1.w;

    {
        long long b = g0 >> OCT_SHIFT;
        long long q = g0 & OCT_MASK;
        float* row = out + b * (long long)L_FULL;
        long long i = 4 * q;
        __stcs(reinterpret_cast<float4*>(row + i), ev0);
        __stcs(reinterpret_cast<float4*>(row + L_HALF + i), od0);
    }
    {
        long long b = g1 >> OCT_SHIFT;
        long long q = g1 & OCT_MASK;
        float* row = out + b * (long long)L_FULL;
        long long i = 4 * q;
        __stcs(reinterpret_cast<float4*>(row + i), ev1);
        __stcs(reinterpret_cast<float4*>(row + L_HALF + i), od1);
    }

    // log_det (and any padding beyond z) = 0
    if (g0 == 0) {
        for (long long i = Z_ELEMS; i < out_size; i++) out[i] = 0.0f;
    }
}

extern "C" void kernel_launch(void* const* d_in, const int* in_sizes, int n_in,
                              void* d_out, int out_size)
{
    const float4* x4 = (const float4*)d_in[0];
    const float*  P  = (const float*)d_in[1];
    const float*  U  = (const float*)d_in[2];
    float* out = (float*)d_out;

    const int blocks = (int)(N_OCTS / OCTS_PER_BLOCK);  // 4096, exact cover
    wavelet_fused_kernel<<<blocks, THREADS>>>(x4, P, U, out, (long long)out_size);
}

// round 8
// speedup vs baseline: 1.1756x; 1.0122x over previous
#include <cuda_runtime.h>

// WaveletNet: 4 lifting steps with length-1 filters == elementwise 2x2 linear map.
// Evens half of each output row: m00*e + m01*o ; details half: m10*e + m11*o,
// with M = prod_{k=3..0} [[1-u_k p_k, u_k], [-p_k, 1]].
// FINAL (R4 champion): 2 octs/thread, 4x front-batched LDG.128 (default-cached),
// 4x STG.128 evict-first stores. Kernel sits at the compulsory-traffic memory
// floor: 128MB combined R+W / ~18.1us ≈ 7.1 TB/s achieved on 8 TB/s-spec HBM3e.
// Verified across 7 structural variants (MLP 1/2/4, 64/128/256-bit ops,
// ca/cs/cg/wt policies): all within 18.0-18.5us kernel — memory-bound wall.

#define L_FULL 65536
#define L_HALF 32768
#define B_DIM  256
#define OCTS_PER_ROW (L_FULL / 8)          // 8192 (one oct = 8 floats = 4 pairs)
#define OCT_SHIFT 13
#define OCT_MASK  (OCTS_PER_ROW - 1)
#define N_OCTS ((long long)B_DIM * OCTS_PER_ROW)   // 2,097,152
#define Z_ELEMS ((long long)B_DIM * L_FULL)        // 16,777,216
#define THREADS 256
#define OCTS_PER_THREAD 2
#define OCTS_PER_BLOCK (THREADS * OCTS_PER_THREAD) // 512

__global__ void __launch_bounds__(THREADS)
wavelet_fused_kernel(const float4* __restrict__ x4,
                     const float* __restrict__ P,
                     const float* __restrict__ U,
                     float* __restrict__ out,
                     long long out_size)
{
    // Compose the 4 lifting steps into one 2x2 matrix (coeffs L1-cached, cheap).
    float m00 = 1.f, m01 = 0.f, m10 = 0.f, m11 = 1.f;
#pragma unroll
    for (int k = 0; k < 4; k++) {
        float p = __ldg(&P[k]);
        float u = __ldg(&U[k]);
        float a00 = 1.f - u * p, a01 = u;
        float a10 = -p,          a11 = 1.f;
        float n00 = a00 * m00 + a01 * m10;
        float n01 = a00 * m01 + a01 * m11;
        float n10 = a10 * m00 + a11 * m10;
        float n11 = a10 * m01 + a11 * m11;
        m00 = n00; m01 = n01; m10 = n10; m11 = n11;
    }

    // Two octs per thread, blockDim apart (both fully coalesced at warp level).
    long long g0 = (long long)blockIdx.x * OCTS_PER_BLOCK + threadIdx.x;
    long long g1 = g0 + THREADS;

    // Front-batched loads: 4 independent LDG.128 before any arithmetic.
    const float4* s0 = x4 + 2 * g0;
    const float4* s1 = x4 + 2 * g1;
    float4 a0 = __ldg(s0);
    float4 a1 = __ldg(s0 + 1);
    float4 b0 = __ldg(s1);
    float4 b1 = __ldg(s1 + 1);

    float4 ev0, od0, ev1, od1;
    ev0.x = m00 * a0.x + m01 * a0.y;  od0.x = m10 * a0.x + m11 * a0.y;
    ev0.y = m00 * a0.z + m01 * a0.w;  od0.y = m10 * a0.z + m11 * a0.w;
    ev0.z = m00 * a1.x + m01 * a1.y;  od0.z = m10 * a1.x + m11 * a1.y;
    ev0.w = m00 * a1.z + m01 * a1.w;  od0.w = m10 * a1.z + m11 * a1.w;

    ev1.x = m00 * b0.x + m01 * b0.y;  od1.x = m10 * b0.x + m11 * b0.y;
    ev1.y = m00 * b0.z + m01 * b0.w;  od1.y = m10 * b0.z + m11 * b0.w;
    ev1.z = m00 * b1.x + m01 * b1.y;  od1.z = m10 * b1.x + m11 * b1.y;
    ev1.w = m00 * b1.z + m01 * b1.w;  od1.w = m10 * b1.z + m11 * b1.w;

    {
        long long b = g0 >> OCT_SHIFT;
        long long q = g0 & OCT_MASK;
        float* row = out + b * (long long)L_FULL;
        long long i = 4 * q;
        __stcs(reinterpret_cast<float4*>(row + i), ev0);
        __stcs(reinterpret_cast<float4*>(row + L_HALF + i), od0);
    }
    {
        long long b = g1 >> OCT_SHIFT;
        long long q = g1 & OCT_MASK;
        float* row = out + b * (long long)L_FULL;
        long long i = 4 * q;
        __stcs(reinterpret_cast<float4*>(row + i), ev1);
        __stcs(reinterpret_cast<float4*>(row + L_HALF + i), od1);
    }

    // log_det (and any padding beyond z) = 0
    if (g0 == 0) {
        for (long long i = Z_ELEMS; i < out_size; i++) out[i] = 0.0f;
    }
}

extern "C" void kernel_launch(void* const* d_in, const int* in_sizes, int n_in,
                              void* d_out, int out_size)
{
    const float4* x4 = (const float4*)d_in[0];
    const float*  P  = (const float*)d_in[1];
    const float*  U  = (const float*)d_in[2];
    float* out = (float*)d_out;

    const int blocks = (int)(N_OCTS / OCTS_PER_BLOCK);  // 4096, exact cover
    wavelet_fused_kernel<<<blocks, THREADS>>>(x4, P, U, out, (long long)out_size);
}